// round 16
// baseline (speedup 1.0000x reference)
#include <cuda_runtime.h>
#include <cuda_fp16.h>
#include <math.h>
#include <stdint.h>

// Problem constants
#define BB   4
#define CC   32
#define HH   64
#define WW   64
#define DD   288          // C*K*K
#define EE   144          // D/2
#define NHD  8            // heads
#define DHH  18           // head dim
#define SFN  4            // split factor
#define NTOK 4096         // H*W tokens per batch
#define NSEG 1024         // NTOK / SF
#define MTOT (BB*NTOK)    // 16384 tokens total

#define WC_ELEMS (3*EE*DD)       // 432x288 combined weight per layer
#define WE_ELEMS (DD*EE)

// ---- f16 mma / ldmatrix / cp.async helpers ---------------------------------
__device__ __forceinline__ void mma_f16(float* c, const uint32_t* a, uint32_t b0, uint32_t b1) {
    asm("mma.sync.aligned.m16n8k16.row.col.f32.f16.f16.f32 "
        "{%0,%1,%2,%3},{%4,%5,%6,%7},{%8,%9},{%0,%1,%2,%3};"
        : "+f"(c[0]), "+f"(c[1]), "+f"(c[2]), "+f"(c[3])
        : "r"(a[0]), "r"(a[1]), "r"(a[2]), "r"(a[3]), "r"(b0), "r"(b1));
}
__device__ __forceinline__ void ldsm_x4(uint32_t* r, uint32_t addr) {
    asm volatile("ldmatrix.sync.aligned.m8n8.x4.shared.b16 {%0,%1,%2,%3},[%4];"
        : "=r"(r[0]), "=r"(r[1]), "=r"(r[2]), "=r"(r[3]) : "r"(addr));
}
__device__ __forceinline__ void ldsm_x2(uint32_t* r, uint32_t addr) {
    asm volatile("ldmatrix.sync.aligned.m8n8.x2.shared.b16 {%0,%1},[%2];"
        : "=r"(r[0]), "=r"(r[1]) : "r"(addr));
}
__device__ __forceinline__ void ldsm_x2t(uint32_t* r, uint32_t addr) {
    asm volatile("ldmatrix.sync.aligned.m8n8.x2.trans.shared.b16 {%0,%1},[%2];"
        : "=r"(r[0]), "=r"(r[1]) : "r"(addr));
}
__device__ __forceinline__ uint32_t cvth2(float lo, float hi) {
    uint32_t r; asm("cvt.rn.f16x2.f32 %0,%1,%2;" : "=r"(r) : "f"(hi), "f"(lo)); return r;
}
__device__ __forceinline__ uint32_t ex2h2(uint32_t x) {
    uint32_t r; asm("ex2.approx.f16x2 %0,%1;" : "=r"(r) : "r"(x)); return r;
}
__device__ __forceinline__ uint32_t packh2(float lo, float hi) {
    __half2 h = __floats2half2_rn(lo, hi);
    return *reinterpret_cast<uint32_t*>(&h);
}
__device__ __forceinline__ void cp16(uint32_t saddr, const void* g) {
    asm volatile("cp.async.ca.shared.global [%0], [%1], 16;" :: "r"(saddr), "l"(g));
}
__device__ __forceinline__ void cp_commit() {
    asm volatile("cp.async.commit_group;");
}
__device__ __forceinline__ void cp_wait1() {
    asm volatile("cp.async.wait_group 1;");
}

// Scratch (device globals: allocation-free rule)
__device__ float  g_t[BB*CC*HH*WW];        // current image (fp32)
__device__ float  g_br[DD*MTOT];           // EMHA branch out, fp32 D-MAJOR [d][tok]
__device__ __half g_colsn_h[MTOT*DD];      // layernormed cols (f16, tok-major)
__device__ __half g_qkv_h[MTOT*3*EE];      // qkv (f16, Q pre-scaled)
__device__ __half g_o_h[MTOT*EE];          // attention output (f16)
__device__ __half g_wc_h[3*WC_ELEMS];      // combined qkv weights (f16), 3 layers
__device__ __half g_we_h[3*WE_ELEMS];      // we (f16), 3 layers
__device__ float  g_bc[3*3*EE];            // combined qkv bias (fp32), 3 layers

struct WPtrs {
    const float* wr[3];
    const float* br[3];
    const float* wqkv[3];
    const float* we[3];
};

// ---------------------------------------------------------------------------
// Combined weight precompute: Wc = wqkv @ wr (f16, Q rows pre-scaled),
// bc = wqkv @ br (fp32, Q rows pre-scaled). One block per (L, f) row.
// ---------------------------------------------------------------------------
__global__ __launch_bounds__(144) void wcomb_kernel(WPtrs p,
                                                    __half* __restrict__ wc,
                                                    float* __restrict__ bc)
{
    int Lf = blockIdx.x;               // 0 .. 3*432-1
    int L = Lf / (3*EE), f = Lf - L * (3*EE);
    const float qs = 0.235702260395515841f * 1.4426950408889634f;
    float scale = (f < EE) ? qs : 1.f;

    __shared__ float sq[EE];
    if (threadIdx.x < EE) sq[threadIdx.x] = p.wqkv[L][(size_t)f*EE + threadIdx.x];
    __syncthreads();

    if (threadIdx.x == 0) {
        float acc = 0.f;
        for (int e = 0; e < EE; e++) acc = fmaf(sq[e], p.br[L][e], acc);
        bc[(L*3*EE) + f] = acc * scale;
    }

    int d = 2 * threadIdx.x;           // 0..286
    float a0 = 0.f, a1 = 0.f;
    const float* wrL = p.wr[L];
    for (int e = 0; e < EE; e++) {
        float s = sq[e];
        float2 w = *reinterpret_cast<const float2*>(&wrL[(size_t)e*DD + d]);
        a0 = fmaf(s, w.x, a0);
        a1 = fmaf(s, w.y, a1);
    }
    uint32_t* out = reinterpret_cast<uint32_t*>(wc);
    out[((size_t)Lf * DD + d) >> 1] = packh2(a0 * scale, a1 * scale);
}

// we conversion fp32 -> f16, all 3 layers
__global__ void weconv_kernel(WPtrs p, __half* __restrict__ dst)
{
    int i = blockIdx.x * 256 + threadIdx.x;
    if (i >= 3 * WE_ELEMS) return;
    int L = i / WE_ELEMS, j = i - L * WE_ELEMS;
    dst[i] = __float2half(p.we[L][j]);
}

// ---------------------------------------------------------------------------
// Fused unfold + LayerNorm. One WARP per token; in-CTA offset table.
// ---------------------------------------------------------------------------
__global__ __launch_bounds__(256) void unfold_ln_kernel(
    const float* __restrict__ img,
    const float* __restrict__ lng,
    const float* __restrict__ lnb)
{
    __shared__ int soff[DD];
    for (int i = threadIdx.x; i < DD; i += 256) {
        int c = i / 9, r = i - 9*c;
        int kh = r / 3, kw = r - 3*kh;
        soff[i] = (c*4096 + (kh-1)*64 + (kw-1) + 65) | (kh << 20) | (kw << 22);
    }
    __syncthreads();

    int warp = threadIdx.x >> 5, lane = threadIdx.x & 31;
    int tok = blockIdx.x * 8 + warp;
    int b = tok >> 12;
    int n = tok & (NTOK - 1);
    int h = n >> 6, w = n & 63;
    int base = b*CC*4096 + h*64 + w;

    float v[9];
    float s = 0.f, q = 0.f;
    if (h >= 1 && h <= 62 && w >= 1 && w <= 62) {
        #pragma unroll
        for (int i = 0; i < 9; i++) {
            int pk = soff[i*32 + lane];
            float x = img[base + (pk & 0xFFFFF) - 65];
            v[i] = x; s += x; q = fmaf(x, x, q);
        }
    } else {
        #pragma unroll
        for (int i = 0; i < 9; i++) {
            int pk = soff[i*32 + lane];
            int kh = (pk >> 20) & 3, kw = (pk >> 22) & 3;
            int hh = h + kh - 1, ww = w + kw - 1;
            float x = 0.f;
            if ((unsigned)hh < HH && (unsigned)ww < WW)
                x = img[base + (pk & 0xFFFFF) - 65];
            v[i] = x; s += x; q = fmaf(x, x, q);
        }
    }
    #pragma unroll
    for (int o = 16; o > 0; o >>= 1) {
        s += __shfl_xor_sync(0xffffffffu, s, o);
        q += __shfl_xor_sync(0xffffffffu, q, o);
    }
    float mu = s * (1.f / DD);
    float rstd = rsqrtf(q * (1.f / DD) - mu * mu + 1e-5f);
    #pragma unroll
    for (int i = 0; i < 9; i++) {
        int d = i * 32 + lane;
        g_colsn_h[(size_t)tok*DD + d] =
            __float2half((v[i] - mu) * rstd * __ldg(&lng[d]) + __ldg(&lnb[d]));
    }
}

// ---------------------------------------------------------------------------
// f16 GEMM, 3-stage cp.async ring + ldmatrix (dynamic smem, 3 CTAs/SM).
// C(M,N) = A(M,K)*W(N,K)^T (+bias). CTA tile 128x48, warp tile 32x24.
// ---------------------------------------------------------------------------
#define APITCH 56
#define BUFHALF (176*APITCH)
#define GEMM_SMEM_BYTES (3*BUFHALF*2)   // 59136

template<int K, bool BOUT>
__global__ __launch_bounds__(256, 3) void gemm_h_kernel(
    const __half* __restrict__ A, const __half* __restrict__ W,
    const float* __restrict__ bias,
    void* __restrict__ Cout, int Ncol)
{
    extern __shared__ __half Sm[];

    int tid = threadIdx.x;
    int warp = tid >> 5, lane = tid & 31;
    int g = lane >> 2, t = lane & 3;
    int wm = warp & 3, wn = warp >> 2;
    int rowB = blockIdx.y * 128;
    int colB = blockIdx.x * 48;

    float acc[2][3][4];
    #pragma unroll
    for (int i = 0; i < 2; i++)
        #pragma unroll
        for (int j = 0; j < 3; j++)
            #pragma unroll
            for (int k = 0; k < 4; k++) acc[i][j][k] = 0.f;

    uint32_t smb = (uint32_t)__cvta_generic_to_shared(Sm);
    int lr = lane & 7, lq = (lane >> 3) & 3;
    uint32_t aoff0 = smb + (((wm*32 + lr + (lq&1)*8) * APITCH + (lq>>1)*8) << 1);
    uint32_t aoff1 = aoff0 + ((16*APITCH) << 1);
    uint32_t boff4 = smb + (((128 + wn*24 + lr + (lq>>1)*8) * APITCH + (lq&1)*8) << 1);
    uint32_t boff2 = smb + (((128 + wn*24 + 16 + lr) * APITCH + ((lane>>3)&1)*8) << 1);

    int ar0 = tid / 6,  as0 = tid - ar0*6;
    int ar1 = (tid+256) / 6, as1 = (tid+256) - ar1*6;
    int ar2 = (tid+512) / 6, as2 = (tid+512) - ar2*6;

    auto stage = [&](int kc, int buf) {
        uint32_t sb = smb + ((buf * BUFHALF) << 1);
        cp16(sb + ((ar0*APITCH + as0*8) << 1), A + (size_t)(rowB + ar0)*K + kc + as0*8);
        cp16(sb + ((ar1*APITCH + as1*8) << 1), A + (size_t)(rowB + ar1)*K + kc + as1*8);
        cp16(sb + ((ar2*APITCH + as2*8) << 1), A + (size_t)(rowB + ar2)*K + kc + as2*8);
        if (tid < 288) {
            int row = tid / 6, seg = tid - row*6;
            cp16(sb + (((128 + row)*APITCH + seg*8) << 1),
                 W + (size_t)(colB + row)*K + kc + seg*8);
        }
        int idx = tid + 256;
        if (idx < 288) {
            int row = idx / 6, seg = idx - row*6;
            cp16(sb + (((128 + row)*APITCH + seg*8) << 1),
                 W + (size_t)(colB + row)*K + kc + seg*8);
        }
        cp_commit();
    };

    const int NCH = K / 48;     // 3 or 6
    stage(0, 0);
    stage(48, 1);

    int buf = 0;
    for (int ch = 0; ch < NCH; ch++) {
        cp_wait1();
        __syncthreads();
        if (ch + 2 < NCH) {
            int nb = buf + 2; if (nb >= 3) nb -= 3;
            stage((ch + 2) * 48, nb);
        } else cp_commit();

        uint32_t bofs = (buf * BUFHALF) << 1;
        #pragma unroll
        for (int kk = 0; kk < 48; kk += 16) {
            uint32_t a0[4], a1[4], b01[4], b2[2];
            ldsm_x4(a0, aoff0 + bofs + (kk << 1));
            ldsm_x4(a1, aoff1 + bofs + (kk << 1));
            ldsm_x4(b01, boff4 + bofs + (kk << 1));
            ldsm_x2(b2, boff2 + bofs + (kk << 1));
            mma_f16(acc[0][0], a0, b01[0], b01[1]);
            mma_f16(acc[0][1], a0, b01[2], b01[3]);
            mma_f16(acc[0][2], a0, b2[0],  b2[1]);
            mma_f16(acc[1][0], a1, b01[0], b01[1]);
            mma_f16(acc[1][1], a1, b01[2], b01[3]);
            mma_f16(acc[1][2], a1, b2[0],  b2[1]);
        }
        __syncthreads();
        buf++; if (buf >= 3) buf = 0;
    }

    #pragma unroll
    for (int mt = 0; mt < 2; mt++) {
        int r0 = rowB + wm*32 + mt*16 + g;
        int r1 = r0 + 8;
        #pragma unroll
        for (int nt = 0; nt < 3; nt++) {
            int cc = colB + wn*24 + nt*8 + 2*t;
            float v0 = acc[mt][nt][0], v1 = acc[mt][nt][1];
            float v2 = acc[mt][nt][2], v3 = acc[mt][nt][3];
            if (bias) {
                float b0 = bias[cc], b1 = bias[cc+1];
                v0 += b0; v1 += b1; v2 += b0; v3 += b1;
            }
            if (BOUT) {
                uint32_t* C = (uint32_t*)Cout;
                C[((size_t)r0 * Ncol + cc) >> 1] = packh2(v0, v1);
                C[((size_t)r1 * Ncol + cc) >> 1] = packh2(v2, v3);
            } else {
                float* C = (float*)Cout;
                size_t i00 = (size_t)cc*MTOT + r0, i10 = i00 + MTOT;
                size_t i01 = (size_t)cc*MTOT + r1, i11 = i01 + MTOT;
                C[i00] = v0; C[i10] = v1; C[i01] = v2; C[i11] = v3;
            }
        }
    }
}

// ---------------------------------------------------------------------------
// Attention: f16 flash, ex2.approx.f16x2, l via ones-column in V (d=18).
// ---------------------------------------------------------------------------
#define KPITCH 40
#define VPITCH 24
#define ATTN_SMEM_BYTES ((NSEG*KPITCH + NSEG*VPITCH) * 2)   // 131072

__global__ __launch_bounds__(512) void attn_kernel()
{
    int seg  = blockIdx.x;
    int b    = seg / (NHD * SFN);
    int rest = seg % (NHD * SFN);
    int hd   = rest / SFN;
    int sp   = rest % SFN;
    int base = b * NTOK + sp * NSEG;
    const int QKVROW = 3 * EE;

    extern __shared__ __half smh[];
    __half* Ks = smh;                       // [NSEG][KPITCH]
    __half* Vs = smh + NSEG * KPITCH;       // [NSEG][VPITCH]

    const uint32_t* qk32 = reinterpret_cast<const uint32_t*>(g_qkv_h);
    uint32_t* Ks32 = reinterpret_cast<uint32_t*>(Ks);
    uint32_t* Vs32 = reinterpret_cast<uint32_t*>(Vs);

    for (int idx = threadIdx.x; idx < NSEG * (KPITCH/2); idx += 512) {
        int i = idx / (KPITCH/2), d2 = idx - i * (KPITCH/2);
        uint32_t v = 0u;
        if (d2 < 9)
            v = qk32[(((size_t)(base + i) * QKVROW + EE + hd * DHH) >> 1) + d2];
        Ks32[i * (KPITCH/2) + d2] = v;
    }
    for (int idx = threadIdx.x; idx < NSEG * (VPITCH/2); idx += 512) {
        int i = idx / (VPITCH/2), d2 = idx - i * (VPITCH/2);
        uint32_t v = 0u;
        if (d2 < 9)
            v = qk32[(((size_t)(base + i) * QKVROW + 2*EE + hd * DHH) >> 1) + d2];
        else if (d2 == 9)
            v = 0x00003C00u;                 // {1.0h, 0} -> l-ones at d=18
        Vs32[i * (VPITCH/2) + d2] = v;
    }
    __syncthreads();

    int lane = threadIdx.x & 31, warp = threadIdx.x >> 5;
    int g = lane >> 2, t = lane & 3;
    int lr = lane & 7, lq = (lane >> 3) & 3;

    uint32_t ksb = (uint32_t)__cvta_generic_to_shared(Ks);
    uint32_t vsb = (uint32_t)__cvta_generic_to_shared(Vs);
    uint32_t kaddr_base = ksb + (((lr + (lq>>1)*8) * KPITCH + (lq&1)*8) << 1);
    uint32_t vaddr_base = vsb + (((lane & 15) * VPITCH) << 1);

    for (int qt = warp; qt < NSEG / 16; qt += 16) {
        int q0 = qt * 16;
        const uint32_t* q32a = qk32 + (((size_t)(base + q0 + g)     * QKVROW + hd * DHH) >> 1);
        const uint32_t* q32b = qk32 + (((size_t)(base + q0 + g + 8) * QKVROW + hd * DHH) >> 1);

        uint32_t qa[2][4];
        qa[0][0] = q32a[t];
        qa[0][1] = q32b[t];
        qa[0][2] = q32a[t + 4];
        qa[0][3] = q32b[t + 4];
        qa[1][0] = (t == 0) ? q32a[8] : 0u;
        qa[1][1] = (t == 0) ? q32b[8] : 0u;
        qa[1][2] = 0u; qa[1][3] = 0u;

        float o[3][4];
        #pragma unroll
        for (int dn = 0; dn < 3; dn++)
            #pragma unroll
            for (int i = 0; i < 4; i++) o[dn][i] = 0.f;

        uint32_t kaddr = kaddr_base;
        uint32_t vaddr = vaddr_base;
        for (int j0 = 0; j0 < NSEG; j0 += 16) {
            uint32_t kf0[4], kf1[4];
            ldsm_x4(kf0, kaddr);
            ldsm_x4(kf1, kaddr + 32);
            float s0[4] = {0.f,0.f,0.f,0.f};
            float s1[4] = {0.f,0.f,0.f,0.f};
            mma_f16(s0, qa[0], kf0[0], kf0[1]);
            mma_f16(s1, qa[0], kf0[2], kf0[3]);
            mma_f16(s0, qa[1], kf1[0], kf1[1]);
            mma_f16(s1, qa[1], kf1[2], kf1[3]);

            uint32_t pa[4];
            pa[0] = ex2h2(cvth2(s0[0], s0[1]));
            pa[1] = ex2h2(cvth2(s0[2], s0[3]));
            pa[2] = ex2h2(cvth2(s1[0], s1[1]));
            pa[3] = ex2h2(cvth2(s1[2], s1[3]));

            uint32_t vf[2];
            ldsm_x2t(vf, vaddr);
            mma_f16(o[0], pa, vf[0], vf[1]);
            ldsm_x2t(vf, vaddr + 16);
            mma_f16(o[1], pa, vf[0], vf[1]);
            ldsm_x2t(vf, vaddr + 32);
            mma_f16(o[2], pa, vf[0], vf[1]);

            kaddr += 16 * KPITCH * 2;
            vaddr += 16 * VPITCH * 2;
        }

        int srcl = (lane & 28) | 1;
        float lg  = __shfl_sync(0xffffffffu, o[2][0], srcl);
        float lg8 = __shfl_sync(0xffffffffu, o[2][2], srcl);
        float ig = 1.f / lg, ig8 = 1.f / lg8;

        uint32_t* o32 = reinterpret_cast<uint32_t*>(g_o_h);
        #pragma unroll
        for (int dn = 0; dn < 3; dn++) {
            int dc = dn * 8 + 2 * t;
            if (dc < DHH) {
                o32[((size_t)(base + q0 + g)     * EE + hd*DHH + dc) >> 1] = packh2(o[dn][0]*ig,  o[dn][1]*ig);
                o32[((size_t)(base + q0 + g + 8) * EE + hd*DHH + dc) >> 1] = packh2(o[dn][2]*ig8, o[dn][3]*ig8);
            }
        }
    }
}

// ---------------------------------------------------------------------------
// Fold: t_next = m(h)·m(w)·t + gather(branch).
// ---------------------------------------------------------------------------
__global__ void fold_kernel(const float* __restrict__ img)
{
    int idx = blockIdx.x * blockDim.x + threadIdx.x;
    if (idx >= BB*CC*HH*WW) return;
    int w = idx & 63;
    int h = (idx >> 6) & 63;
    int c = (idx >> 12) & 31;
    int b =  idx >> 17;

    float mh = (h == 0 || h == HH-1) ? 2.f : 3.f;
    float mw = (w == 0 || w == WW-1) ? 2.f : 3.f;
    float sum = img[idx] * (mh * mw);

    #pragma unroll
    for (int i = 0; i < 3; i++) {
        int hh = h + 1 - i;
        if (hh < 0 || hh >= HH) continue;
        #pragma unroll
        for (int j = 0; j < 3; j++) {
            int ww = w + 1 - j;
            if (ww < 0 || ww >= WW) continue;
            sum += g_br[(size_t)(c*9 + i*3 + j)*MTOT + b*NTOK + hh*WW + ww];
        }
    }
    g_t[idx] = sum;
}

// ---------------------------------------------------------------------------
// Final: out = x + elu(conv3x3(t) + conv_b). Two adjacent-w outputs/thread.
// ---------------------------------------------------------------------------
__global__ __launch_bounds__(256) void conv_elu_kernel(
    const float* __restrict__ x,
    const float* __restrict__ cw,
    const float* __restrict__ cb,
    float* __restrict__ out)
{
    int idx = blockIdx.x * blockDim.x + threadIdx.x;   // over NPIX/2
    if (idx >= BB*CC*HH*WW/2) return;
    int wp = idx & 31;
    int h  = (idx >> 5) & 63;
    int co = (idx >> 11) & 31;
    int b  =  idx >> 16;
    int w = wp * 2;

    float s0 = cb[co], s1 = s0;
    for (int ci = 0; ci < CC; ci++) {
        const float* tplane = &g_t[((size_t)(b*CC + ci))*HH*WW];
        const float* wk = &cw[((size_t)(co*CC + ci))*9];
        #pragma unroll
        for (int kh = 0; kh < 3; kh++) {
            int hh = h + kh - 1;
            if ((unsigned)hh >= HH) continue;
            const float* row = tplane + hh*WW;
            float r0 = (w >= 1)      ? row[w-1] : 0.f;
            float r1 = row[w];
            float r2 = row[w+1];
            float r3 = (w+2 <= 63)   ? row[w+2] : 0.f;
            float w0 = wk[kh*3+0], w1 = wk[kh*3+1], w2 = wk[kh*3+2];
            s0 = fmaf(w0, r0, fmaf(w1, r1, fmaf(w2, r2, s0)));
            s1 = fmaf(w0, r1, fmaf(w1, r2, fmaf(w2, r3, s1)));
        }
    }
    size_t o = ((size_t)(b*CC + co)*HH + h)*WW + w;
    float e0 = s0 > 0.f ? s0 : expm1f(s0);
    float e1 = s1 > 0.f ? s1 : expm1f(s1);
    out[o]   = x[o]   + e0;
    out[o+1] = x[o+1] + e1;
}

// ---------------------------------------------------------------------------
// Launch
// ---------------------------------------------------------------------------
extern "C" void kernel_launch(void* const* d_in, const int* in_sizes, int n_in,
                              void* d_out, int out_size)
{
    (void)in_sizes; (void)n_in; (void)out_size;
    const float* x     = (const float*)d_in[0];
    const float* ln_g  = (const float*)d_in[1];
    const float* ln_b  = (const float*)d_in[2];
    const float* convw = (const float*)d_in[3];
    const float* convb = (const float*)d_in[4];
    float* out = (float*)d_out;

    float *p_t, *p_br, *p_bc;
    __half *p_colsn, *p_qkv, *p_o, *p_wc, *p_we;
    cudaGetSymbolAddress((void**)&p_t,     g_t);
    cudaGetSymbolAddress((void**)&p_br,    g_br);
    cudaGetSymbolAddress((void**)&p_colsn, g_colsn_h);
    cudaGetSymbolAddress((void**)&p_qkv,   g_qkv_h);
    cudaGetSymbolAddress((void**)&p_o,     g_o_h);
    cudaGetSymbolAddress((void**)&p_wc,    g_wc_h);
    cudaGetSymbolAddress((void**)&p_we,    g_we_h);
    cudaGetSymbolAddress((void**)&p_bc,    g_bc);

    cudaFuncSetAttribute(attn_kernel, cudaFuncAttributeMaxDynamicSharedMemorySize, ATTN_SMEM_BYTES);
    cudaFuncSetAttribute(gemm_h_kernel<288, true>,
                         cudaFuncAttributeMaxDynamicSharedMemorySize, GEMM_SMEM_BYTES);
    cudaFuncSetAttribute(gemm_h_kernel<144, false>,
                         cudaFuncAttributeMaxDynamicSharedMemorySize, GEMM_SMEM_BYTES);

    const int NPIX = BB*CC*HH*WW;

    WPtrs wp;
    for (int L = 0; L < 3; L++) {
        wp.wr[L]   = (const float*)d_in[5 + 5*L + 0];
        wp.br[L]   = (const float*)d_in[5 + 5*L + 1];
        wp.wqkv[L] = (const float*)d_in[5 + 5*L + 2];
        wp.we[L]   = (const float*)d_in[5 + 5*L + 3];
    }
    wcomb_kernel<<<3*3*EE, 144>>>(wp, p_wc, p_bc);
    weconv_kernel<<<(3*WE_ELEMS + 255)/256, 256>>>(wp, p_we);

    for (int L = 0; L < 3; L++) {
        const float* be = (const float*)d_in[5 + 5*L + 4];
        const __half* wc = p_wc + (size_t)L * WC_ELEMS;
        const __half* we = p_we + (size_t)L * WE_ELEMS;
        const float*  bc = p_bc + (size_t)L * 3*EE;
        const float* img = (L == 0) ? x : p_t;

        unfold_ln_kernel<<<MTOT/8, 256>>>(img, ln_g, ln_b);
        // qkv = colsn @ Wc^T + bc   (fused GEMM1+GEMM2, K=288, N=432)
        gemm_h_kernel<288, true><<<dim3(3*EE/48, MTOT/128), 256, GEMM_SMEM_BYTES>>>(
            p_colsn, wc, bc, p_qkv, 3*EE);
        attn_kernel<<<BB*NHD*SFN, 512, ATTN_SMEM_BYTES>>>();
        // branch = o @ we^T + be    (fp32 d-major out)
        gemm_h_kernel<144, false><<<dim3(DD/48, MTOT/128), 256, GEMM_SMEM_BYTES>>>(
            p_o, we, be, p_br, DD);
        fold_kernel<<<(NPIX + 255)/256, 256>>>(img);
    }
    conv_elu_kernel<<<(NPIX/2 + 255)/256, 256>>>(x, convw, convb, out);
}

// round 17
// speedup vs baseline: 1.0421x; 1.0421x over previous
#include <cuda_runtime.h>
#include <cuda_fp16.h>
#include <math.h>
#include <stdint.h>

// Problem constants
#define BB   4
#define CC   32
#define HH   64
#define WW   64
#define DD   288          // C*K*K
#define EE   144          // D/2
#define NHD  8            // heads
#define DHH  18           // head dim
#define SFN  4            // split factor
#define NTOK 4096         // H*W tokens per batch
#define NSEG 1024         // NTOK / SF
#define MTOT (BB*NTOK)    // 16384 tokens total

// weight buffer layout (f16), per layer
#define WR_ELEMS   (EE*DD)
#define WQKV_ELEMS (3*EE*EE)
#define WE_ELEMS   (DD*EE)
#define WL_STRIDE  (WR_ELEMS + WQKV_ELEMS + WE_ELEMS)
#define WQKV_OFF   WR_ELEMS
#define WE_OFF     (WR_ELEMS + WQKV_ELEMS)

// ---- f16 mma / ldmatrix / cp.async helpers ---------------------------------
__device__ __forceinline__ void mma_f16(float* c, const uint32_t* a, uint32_t b0, uint32_t b1) {
    asm("mma.sync.aligned.m16n8k16.row.col.f32.f16.f16.f32 "
        "{%0,%1,%2,%3},{%4,%5,%6,%7},{%8,%9},{%0,%1,%2,%3};"
        : "+f"(c[0]), "+f"(c[1]), "+f"(c[2]), "+f"(c[3])
        : "r"(a[0]), "r"(a[1]), "r"(a[2]), "r"(a[3]), "r"(b0), "r"(b1));
}
__device__ __forceinline__ void ldsm_x4(uint32_t* r, uint32_t addr) {
    asm volatile("ldmatrix.sync.aligned.m8n8.x4.shared.b16 {%0,%1,%2,%3},[%4];"
        : "=r"(r[0]), "=r"(r[1]), "=r"(r[2]), "=r"(r[3]) : "r"(addr));
}
__device__ __forceinline__ void ldsm_x2(uint32_t* r, uint32_t addr) {
    asm volatile("ldmatrix.sync.aligned.m8n8.x2.shared.b16 {%0,%1},[%2];"
        : "=r"(r[0]), "=r"(r[1]) : "r"(addr));
}
__device__ __forceinline__ void ldsm_x2t(uint32_t* r, uint32_t addr) {
    asm volatile("ldmatrix.sync.aligned.m8n8.x2.trans.shared.b16 {%0,%1},[%2];"
        : "=r"(r[0]), "=r"(r[1]) : "r"(addr));
}
__device__ __forceinline__ uint32_t cvth2(float lo, float hi) {
    uint32_t r; asm("cvt.rn.f16x2.f32 %0,%1,%2;" : "=r"(r) : "f"(hi), "f"(lo)); return r;
}
__device__ __forceinline__ uint32_t ex2h2(uint32_t x) {
    uint32_t r; asm("ex2.approx.f16x2 %0,%1;" : "=r"(r) : "r"(x)); return r;
}
__device__ __forceinline__ uint32_t packh2(float lo, float hi) {
    __half2 h = __floats2half2_rn(lo, hi);
    return *reinterpret_cast<uint32_t*>(&h);
}
__device__ __forceinline__ void cp16(uint32_t saddr, const void* g) {
    asm volatile("cp.async.ca.shared.global [%0], [%1], 16;" :: "r"(saddr), "l"(g));
}
__device__ __forceinline__ void cp_commit() {
    asm volatile("cp.async.commit_group;");
}
__device__ __forceinline__ void cp_wait1() {
    asm volatile("cp.async.wait_group 1;");
}

// Scratch (device globals: allocation-free rule)
__device__ float  g_t[BB*CC*HH*WW];        // current image (fp32)
__device__ float  g_br[DD*MTOT];           // EMHA branch out, fp32 D-MAJOR [d][tok]
__device__ __half g_colsn_h[MTOT*DD];      // layernormed cols (f16, tok-major)
__device__ __half g_xr_h[MTOT*EE];         // reduced tokens (f16)
__device__ __half g_qkv_h[MTOT*3*EE];      // qkv (f16, Q pre-scaled)
__device__ __half g_o_h[MTOT*EE];          // attention output (f16)
__device__ __half g_w_h[3*WL_STRIDE];      // converted weights, 3 layers

// ---------------------------------------------------------------------------
// Weight conversion fp32 -> f16, all 3 layers in ONE launch.
// ---------------------------------------------------------------------------
struct WPtrs {
    const float* wr[3];
    const float* wqkv[3];
    const float* we[3];
};
__global__ void wconv_kernel(WPtrs p, __half* __restrict__ dst)
{
    const float qs = 0.235702260395515841f * 1.4426950408889634f;
    int i = blockIdx.x * 256 + threadIdx.x;
    if (i >= 3 * WL_STRIDE) return;
    int L = i / WL_STRIDE;
    int j = i - L * WL_STRIDE;
    float v;
    if (j < WR_ELEMS) v = p.wr[L][j];
    else if (j < WE_OFF) {
        int k = j - WQKV_OFF;
        v = p.wqkv[L][k];
        if (k < EE * EE) v *= qs;
    } else v = p.we[L][j - WE_OFF];
    dst[i] = __float2half(v);
}

// ---------------------------------------------------------------------------
// Fused unfold + LayerNorm. One WARP per token; in-CTA offset table.
// ---------------------------------------------------------------------------
__global__ __launch_bounds__(256) void unfold_ln_kernel(
    const float* __restrict__ img,
    const float* __restrict__ lng,
    const float* __restrict__ lnb)
{
    __shared__ int soff[DD];
    for (int i = threadIdx.x; i < DD; i += 256) {
        int c = i / 9, r = i - 9*c;
        int kh = r / 3, kw = r - 3*kh;
        soff[i] = (c*4096 + (kh-1)*64 + (kw-1) + 65) | (kh << 20) | (kw << 22);
    }
    __syncthreads();

    int warp = threadIdx.x >> 5, lane = threadIdx.x & 31;
    int tok = blockIdx.x * 8 + warp;
    int b = tok >> 12;
    int n = tok & (NTOK - 1);
    int h = n >> 6, w = n & 63;
    int base = b*CC*4096 + h*64 + w;

    float v[9];
    float s = 0.f, q = 0.f;
    if (h >= 1 && h <= 62 && w >= 1 && w <= 62) {
        #pragma unroll
        for (int i = 0; i < 9; i++) {
            int pk = soff[i*32 + lane];
            float x = img[base + (pk & 0xFFFFF) - 65];
            v[i] = x; s += x; q = fmaf(x, x, q);
        }
    } else {
        #pragma unroll
        for (int i = 0; i < 9; i++) {
            int pk = soff[i*32 + lane];
            int kh = (pk >> 20) & 3, kw = (pk >> 22) & 3;
            int hh = h + kh - 1, ww = w + kw - 1;
            float x = 0.f;
            if ((unsigned)hh < HH && (unsigned)ww < WW)
                x = img[base + (pk & 0xFFFFF) - 65];
            v[i] = x; s += x; q = fmaf(x, x, q);
        }
    }
    #pragma unroll
    for (int o = 16; o > 0; o >>= 1) {
        s += __shfl_xor_sync(0xffffffffu, s, o);
        q += __shfl_xor_sync(0xffffffffu, q, o);
    }
    float mu = s * (1.f / DD);
    float rstd = rsqrtf(q * (1.f / DD) - mu * mu + 1e-5f);
    #pragma unroll
    for (int i = 0; i < 9; i++) {
        int d = i * 32 + lane;
        g_colsn_h[(size_t)tok*DD + d] =
            __float2half((v[i] - mu) * rstd * __ldg(&lng[d]) + __ldg(&lnb[d]));
    }
}

// ---------------------------------------------------------------------------
// f16 GEMM, 3-stage cp.async ring + ldmatrix, WIDE tile: CTA 128x72,
// 384 thr = 12 warps (4M x 3N), warp tile 32x24, k-chunk 48.
// A rows 0..127, B rows 128..199 in each smem buffer.
// BOUT=true: f16 packed tok-major out. BOUT=false: fp32 D-MAJOR out.
// ---------------------------------------------------------------------------
#define APITCH 56
#define BUFHALF (200*APITCH)
#define GEMM_SMEM_BYTES (3*BUFHALF*2)   // 67200

template<int K, bool BOUT>
__global__ __launch_bounds__(384, 2) void gemm_h_kernel(
    const __half* __restrict__ A, const __half* __restrict__ W,
    const float* __restrict__ bias,
    void* __restrict__ Cout, int Ncol)
{
    extern __shared__ __half Sm[];

    int tid = threadIdx.x;
    int warp = tid >> 5, lane = tid & 31;
    int g = lane >> 2, t = lane & 3;
    int wm = warp & 3, wn = warp >> 2;      // 4M x 3N
    int rowB = blockIdx.y * 128;
    int colB = blockIdx.x * 72;

    float acc[2][3][4];
    #pragma unroll
    for (int i = 0; i < 2; i++)
        #pragma unroll
        for (int j = 0; j < 3; j++)
            #pragma unroll
            for (int k = 0; k < 4; k++) acc[i][j][k] = 0.f;

    uint32_t smb = (uint32_t)__cvta_generic_to_shared(Sm);
    int lr = lane & 7, lq = (lane >> 3) & 3;
    uint32_t aoff0 = smb + (((wm*32 + lr + (lq&1)*8) * APITCH + (lq>>1)*8) << 1);
    uint32_t aoff1 = aoff0 + ((16*APITCH) << 1);
    uint32_t boff4 = smb + (((128 + wn*24 + lr + (lq>>1)*8) * APITCH + (lq&1)*8) << 1);
    uint32_t boff2 = smb + (((128 + wn*24 + 16 + lr) * APITCH + ((lane>>3)&1)*8) << 1);

    // staging lane roles: A 768 chunks (2/thread), B 432 chunks (1 + spill)
    int ar0 = tid / 6,        as0 = tid - ar0*6;
    int ar1 = (tid+384) / 6,  as1 = (tid+384) - ar1*6;
    int br0 = tid / 6,        bs0 = as0;            // B rows 0..63
    int br1 = (tid+384) / 6,  bs1 = as1;            // B rows 64..71 (tid<48)

    auto stage = [&](int kc, int buf) {
        uint32_t sb = smb + ((buf * BUFHALF) << 1);
        cp16(sb + ((ar0*APITCH + as0*8) << 1), A + (size_t)(rowB + ar0)*K + kc + as0*8);
        cp16(sb + ((ar1*APITCH + as1*8) << 1), A + (size_t)(rowB + ar1)*K + kc + as1*8);
        cp16(sb + (((128 + br0)*APITCH + bs0*8) << 1),
             W + (size_t)(colB + br0)*K + kc + bs0*8);
        if (tid < 48)
            cp16(sb + (((128 + br1)*APITCH + bs1*8) << 1),
                 W + (size_t)(colB + br1)*K + kc + bs1*8);
        cp_commit();
    };

    const int NCH = K / 48;     // 3 or 6
    stage(0, 0);
    stage(48, 1);

    int buf = 0;
    for (int ch = 0; ch < NCH; ch++) {
        cp_wait1();
        __syncthreads();
        if (ch + 2 < NCH) {
            int nb = buf + 2; if (nb >= 3) nb -= 3;
            stage((ch + 2) * 48, nb);
        } else cp_commit();

        uint32_t bofs = (buf * BUFHALF) << 1;
        #pragma unroll
        for (int kk = 0; kk < 48; kk += 16) {
            uint32_t a0[4], a1[4], b01[4], b2[2];
            ldsm_x4(a0, aoff0 + bofs + (kk << 1));
            ldsm_x4(a1, aoff1 + bofs + (kk << 1));
            ldsm_x4(b01, boff4 + bofs + (kk << 1));
            ldsm_x2(b2, boff2 + bofs + (kk << 1));
            mma_f16(acc[0][0], a0, b01[0], b01[1]);
            mma_f16(acc[0][1], a0, b01[2], b01[3]);
            mma_f16(acc[0][2], a0, b2[0],  b2[1]);
            mma_f16(acc[1][0], a1, b01[0], b01[1]);
            mma_f16(acc[1][1], a1, b01[2], b01[3]);
            mma_f16(acc[1][2], a1, b2[0],  b2[1]);
        }
        __syncthreads();
        buf++; if (buf >= 3) buf = 0;
    }

    #pragma unroll
    for (int mt = 0; mt < 2; mt++) {
        int r0 = rowB + wm*32 + mt*16 + g;
        int r1 = r0 + 8;
        #pragma unroll
        for (int nt = 0; nt < 3; nt++) {
            int cc = colB + wn*24 + nt*8 + 2*t;
            float v0 = acc[mt][nt][0], v1 = acc[mt][nt][1];
            float v2 = acc[mt][nt][2], v3 = acc[mt][nt][3];
            if (bias) {
                float b0 = bias[cc], b1 = bias[cc+1];
                v0 += b0; v1 += b1; v2 += b0; v3 += b1;
            }
            if (BOUT) {
                uint32_t* C = (uint32_t*)Cout;
                C[((size_t)r0 * Ncol + cc) >> 1] = packh2(v0, v1);
                C[((size_t)r1 * Ncol + cc) >> 1] = packh2(v2, v3);
            } else {
                float* C = (float*)Cout;
                size_t i00 = (size_t)cc*MTOT + r0, i10 = i00 + MTOT;
                size_t i01 = (size_t)cc*MTOT + r1, i11 = i01 + MTOT;
                C[i00] = v0; C[i10] = v1; C[i01] = v2; C[i11] = v3;
            }
        }
    }
}

// ---------------------------------------------------------------------------
// Attention: f16 flash, ex2.approx.f16x2, l via ones-column in V (d=18).
// ---------------------------------------------------------------------------
#define KPITCH 40
#define VPITCH 24
#define ATTN_SMEM_BYTES ((NSEG*KPITCH + NSEG*VPITCH) * 2)   // 131072

__global__ __launch_bounds__(512) void attn_kernel()
{
    int seg  = blockIdx.x;
    int b    = seg / (NHD * SFN);
    int rest = seg % (NHD * SFN);
    int hd   = rest / SFN;
    int sp   = rest % SFN;
    int base = b * NTOK + sp * NSEG;
    const int QKVROW = 3 * EE;

    extern __shared__ __half smh[];
    __half* Ks = smh;                       // [NSEG][KPITCH]
    __half* Vs = smh + NSEG * KPITCH;       // [NSEG][VPITCH]

    const uint32_t* qk32 = reinterpret_cast<const uint32_t*>(g_qkv_h);
    uint32_t* Ks32 = reinterpret_cast<uint32_t*>(Ks);
    uint32_t* Vs32 = reinterpret_cast<uint32_t*>(Vs);

    for (int idx = threadIdx.x; idx < NSEG * (KPITCH/2); idx += 512) {
        int i = idx / (KPITCH/2), d2 = idx - i * (KPITCH/2);
        uint32_t v = 0u;
        if (d2 < 9)
            v = qk32[(((size_t)(base + i) * QKVROW + EE + hd * DHH) >> 1) + d2];
        Ks32[i * (KPITCH/2) + d2] = v;
    }
    for (int idx = threadIdx.x; idx < NSEG * (VPITCH/2); idx += 512) {
        int i = idx / (VPITCH/2), d2 = idx - i * (VPITCH/2);
        uint32_t v = 0u;
        if (d2 < 9)
            v = qk32[(((size_t)(base + i) * QKVROW + 2*EE + hd * DHH) >> 1) + d2];
        else if (d2 == 9)
            v = 0x00003C00u;                 // {1.0h, 0} -> l-ones at d=18
        Vs32[i * (VPITCH/2) + d2] = v;
    }
    __syncthreads();

    int lane = threadIdx.x & 31, warp = threadIdx.x >> 5;
    int g = lane >> 2, t = lane & 3;
    int lr = lane & 7, lq = (lane >> 3) & 3;

    uint32_t ksb = (uint32_t)__cvta_generic_to_shared(Ks);
    uint32_t vsb = (uint32_t)__cvta_generic_to_shared(Vs);
    uint32_t kaddr_base = ksb + (((lr + (lq>>1)*8) * KPITCH + (lq&1)*8) << 1);
    uint32_t vaddr_base = vsb + (((lane & 15) * VPITCH) << 1);

    for (int qt = warp; qt < NSEG / 16; qt += 16) {
        int q0 = qt * 16;
        const uint32_t* q32a = qk32 + (((size_t)(base + q0 + g)     * QKVROW + hd * DHH) >> 1);
        const uint32_t* q32b = qk32 + (((size_t)(base + q0 + g + 8) * QKVROW + hd * DHH) >> 1);

        uint32_t qa[2][4];
        qa[0][0] = q32a[t];
        qa[0][1] = q32b[t];
        qa[0][2] = q32a[t + 4];
        qa[0][3] = q32b[t + 4];
        qa[1][0] = (t == 0) ? q32a[8] : 0u;
        qa[1][1] = (t == 0) ? q32b[8] : 0u;
        qa[1][2] = 0u; qa[1][3] = 0u;

        float o[3][4];
        #pragma unroll
        for (int dn = 0; dn < 3; dn++)
            #pragma unroll
            for (int i = 0; i < 4; i++) o[dn][i] = 0.f;

        uint32_t kaddr = kaddr_base;
        uint32_t vaddr = vaddr_base;
        for (int j0 = 0; j0 < NSEG; j0 += 16) {
            uint32_t kf0[4], kf1[4];
            ldsm_x4(kf0, kaddr);
            ldsm_x4(kf1, kaddr + 32);
            float s0[4] = {0.f,0.f,0.f,0.f};
            float s1[4] = {0.f,0.f,0.f,0.f};
            mma_f16(s0, qa[0], kf0[0], kf0[1]);
            mma_f16(s1, qa[0], kf0[2], kf0[3]);
            mma_f16(s0, qa[1], kf1[0], kf1[1]);
            mma_f16(s1, qa[1], kf1[2], kf1[3]);

            uint32_t pa[4];
            pa[0] = ex2h2(cvth2(s0[0], s0[1]));
            pa[1] = ex2h2(cvth2(s0[2], s0[3]));
            pa[2] = ex2h2(cvth2(s1[0], s1[1]));
            pa[3] = ex2h2(cvth2(s1[2], s1[3]));

            uint32_t vf[2];
            ldsm_x2t(vf, vaddr);
            mma_f16(o[0], pa, vf[0], vf[1]);
            ldsm_x2t(vf, vaddr + 16);
            mma_f16(o[1], pa, vf[0], vf[1]);
            ldsm_x2t(vf, vaddr + 32);
            mma_f16(o[2], pa, vf[0], vf[1]);

            kaddr += 16 * KPITCH * 2;
            vaddr += 16 * VPITCH * 2;
        }

        int srcl = (lane & 28) | 1;
        float lg  = __shfl_sync(0xffffffffu, o[2][0], srcl);
        float lg8 = __shfl_sync(0xffffffffu, o[2][2], srcl);
        float ig = 1.f / lg, ig8 = 1.f / lg8;

        uint32_t* o32 = reinterpret_cast<uint32_t*>(g_o_h);
        #pragma unroll
        for (int dn = 0; dn < 3; dn++) {
            int dc = dn * 8 + 2 * t;
            if (dc < DHH) {
                o32[((size_t)(base + q0 + g)     * EE + hd*DHH + dc) >> 1] = packh2(o[dn][0]*ig,  o[dn][1]*ig);
                o32[((size_t)(base + q0 + g + 8) * EE + hd*DHH + dc) >> 1] = packh2(o[dn][2]*ig8, o[dn][3]*ig8);
            }
        }
    }
}

// ---------------------------------------------------------------------------
// Fold: t_next = m(h)·m(w)·t + gather(branch).
// ---------------------------------------------------------------------------
__global__ void fold_kernel(const float* __restrict__ img)
{
    int idx = blockIdx.x * blockDim.x + threadIdx.x;
    if (idx >= BB*CC*HH*WW) return;
    int w = idx & 63;
    int h = (idx >> 6) & 63;
    int c = (idx >> 12) & 31;
    int b =  idx >> 17;

    float mh = (h == 0 || h == HH-1) ? 2.f : 3.f;
    float mw = (w == 0 || w == WW-1) ? 2.f : 3.f;
    float sum = img[idx] * (mh * mw);

    #pragma unroll
    for (int i = 0; i < 3; i++) {
        int hh = h + 1 - i;
        if (hh < 0 || hh >= HH) continue;
        #pragma unroll
        for (int j = 0; j < 3; j++) {
            int ww = w + 1 - j;
            if (ww < 0 || ww >= WW) continue;
            sum += g_br[(size_t)(c*9 + i*3 + j)*MTOT + b*NTOK + hh*WW + ww];
        }
    }
    g_t[idx] = sum;
}

// ---------------------------------------------------------------------------
// Final: out = x + elu(conv3x3(t) + conv_b). Two adjacent-w outputs/thread.
// ---------------------------------------------------------------------------
__global__ __launch_bounds__(256) void conv_elu_kernel(
    const float* __restrict__ x,
    const float* __restrict__ cw,
    const float* __restrict__ cb,
    float* __restrict__ out)
{
    int idx = blockIdx.x * blockDim.x + threadIdx.x;   // over NPIX/2
    if (idx >= BB*CC*HH*WW/2) return;
    int wp = idx & 31;
    int h  = (idx >> 5) & 63;
    int co = (idx >> 11) & 31;
    int b  =  idx >> 16;
    int w = wp * 2;

    float s0 = cb[co], s1 = s0;
    for (int ci = 0; ci < CC; ci++) {
        const float* tplane = &g_t[((size_t)(b*CC + ci))*HH*WW];
        const float* wk = &cw[((size_t)(co*CC + ci))*9];
        #pragma unroll
        for (int kh = 0; kh < 3; kh++) {
            int hh = h + kh - 1;
            if ((unsigned)hh >= HH) continue;
            const float* row = tplane + hh*WW;
            float r0 = (w >= 1)      ? row[w-1] : 0.f;
            float r1 = row[w];
            float r2 = row[w+1];
            float r3 = (w+2 <= 63)   ? row[w+2] : 0.f;
            float w0 = wk[kh*3+0], w1 = wk[kh*3+1], w2 = wk[kh*3+2];
            s0 = fmaf(w0, r0, fmaf(w1, r1, fmaf(w2, r2, s0)));
            s1 = fmaf(w0, r1, fmaf(w1, r2, fmaf(w2, r3, s1)));
        }
    }
    size_t o = ((size_t)(b*CC + co)*HH + h)*WW + w;
    float e0 = s0 > 0.f ? s0 : expm1f(s0);
    float e1 = s1 > 0.f ? s1 : expm1f(s1);
    out[o]   = x[o]   + e0;
    out[o+1] = x[o+1] + e1;
}

// ---------------------------------------------------------------------------
// Launch
// ---------------------------------------------------------------------------
extern "C" void kernel_launch(void* const* d_in, const int* in_sizes, int n_in,
                              void* d_out, int out_size)
{
    (void)in_sizes; (void)n_in; (void)out_size;
    const float* x     = (const float*)d_in[0];
    const float* ln_g  = (const float*)d_in[1];
    const float* ln_b  = (const float*)d_in[2];
    const float* convw = (const float*)d_in[3];
    const float* convb = (const float*)d_in[4];
    float* out = (float*)d_out;

    float *p_t, *p_br;
    __half *p_colsn, *p_xr, *p_qkv, *p_o, *p_w;
    cudaGetSymbolAddress((void**)&p_t,     g_t);
    cudaGetSymbolAddress((void**)&p_br,    g_br);
    cudaGetSymbolAddress((void**)&p_colsn, g_colsn_h);
    cudaGetSymbolAddress((void**)&p_xr,    g_xr_h);
    cudaGetSymbolAddress((void**)&p_qkv,   g_qkv_h);
    cudaGetSymbolAddress((void**)&p_o,     g_o_h);
    cudaGetSymbolAddress((void**)&p_w,     g_w_h);

    cudaFuncSetAttribute(attn_kernel, cudaFuncAttributeMaxDynamicSharedMemorySize, ATTN_SMEM_BYTES);
    cudaFuncSetAttribute(gemm_h_kernel<288, true>,
                         cudaFuncAttributeMaxDynamicSharedMemorySize, GEMM_SMEM_BYTES);
    cudaFuncSetAttribute(gemm_h_kernel<144, true>,
                         cudaFuncAttributeMaxDynamicSharedMemorySize, GEMM_SMEM_BYTES);
    cudaFuncSetAttribute(gemm_h_kernel<144, false>,
                         cudaFuncAttributeMaxDynamicSharedMemorySize, GEMM_SMEM_BYTES);

    const int NPIX = BB*CC*HH*WW;

    WPtrs wp;
    for (int L = 0; L < 3; L++) {
        wp.wr[L]   = (const float*)d_in[5 + 5*L + 0];
        wp.wqkv[L] = (const float*)d_in[5 + 5*L + 2];
        wp.we[L]   = (const float*)d_in[5 + 5*L + 3];
    }
    wconv_kernel<<<(3*WL_STRIDE + 255)/256, 256>>>(wp, p_w);

    for (int L = 0; L < 3; L++) {
        const float* br = (const float*)d_in[5 + 5*L + 1];
        const float* be = (const float*)d_in[5 + 5*L + 4];
        const __half* wr   = p_w + (size_t)L * WL_STRIDE;
        const __half* wqkv = wr + WQKV_OFF;
        const __half* we   = wr + WE_OFF;
        const float* img = (L == 0) ? x : p_t;

        unfold_ln_kernel<<<MTOT/8, 256>>>(img, ln_g, ln_b);
        // xr = colsn @ wr^T + br     (N=144 -> 2 col-blocks)
        gemm_h_kernel<288, true><<<dim3(EE/72, MTOT/128), 384, GEMM_SMEM_BYTES>>>(
            p_colsn, wr, br, p_xr, EE);
        // qkv = xr @ wqkv^T          (N=432 -> 6 col-blocks)
        gemm_h_kernel<144, true><<<dim3(3*EE/72, MTOT/128), 384, GEMM_SMEM_BYTES>>>(
            p_xr, wqkv, nullptr, p_qkv, 3*EE);
        attn_kernel<<<BB*NHD*SFN, 512, ATTN_SMEM_BYTES>>>();
        // branch = o @ we^T + be     (N=288 -> 4 col-blocks)
        gemm_h_kernel<144, false><<<dim3(DD/72, MTOT/128), 384, GEMM_SMEM_BYTES>>>(
            p_o, we, be, p_br, DD);
        fold_kernel<<<(NPIX + 255)/256, 256>>>(img);
    }
    conv_elu_kernel<<<(NPIX/2 + 255)/256, 256>>>(x, convw, convb, out);
}